// round 11
// baseline (speedup 1.0000x reference)
#include <cuda_runtime.h>
#include <cuda_fp16.h>

typedef unsigned long long u64;

#define Nn   200000
#define Ee   3200000
#define Bb   512
#define EMB  32
#define HID  64
#define TILE 1024
#define NT   ((Nn + TILE - 1) / TILE)   // 196 scan tiles
#define NPB  256                        // nodes per block in layer kernels
#define NBLK ((Nn + NPB - 1) / NPB)

// dynamic smem sizes
#define SMEM1 ((2*EMB*HID + HID)*4 + NPB*4*16*2)   // 49408 B
#define SMEM2 ((2*HID*HID + HID)*4 + NPB*8*16*2)   // 98560 B

// ---------------- scratch (device globals) ----------------
__device__ uint4 g_h0h [Nn * 4];          // 12.8 MB fp16 h0
__device__ uint4 g_h1h [Nn * 8];          // 25.6 MB fp16 h1
__device__ int   g_csr [Ee];              // 12.8 MB
__device__ int   g_rank[Ee];              // 12.8 MB edge rank within dst
__device__ int   g_rowptr[Nn];
__device__ int   g_deg [Nn];
__device__ float g_dinv[Nn];
__device__ float g_hg  [Bb * HID];
__device__ float g_cnt [Bb];
__device__ volatile unsigned g_tilest[NT];
__device__ int   g_ticket;

// ---------------- helpers ----------------
__device__ __forceinline__ void red4(float4* p, float4 v) {
    asm volatile("red.global.add.v4.f32 [%0], {%1,%2,%3,%4};"
                 :: "l"(p), "f"(v.x), "f"(v.y), "f"(v.z), "f"(v.w) : "memory");
}
__device__ __forceinline__ u64 pack2(float x, float y) {
    u64 r; asm("mov.b64 %0, {%1, %2};" : "=l"(r) : "f"(x), "f"(y)); return r;
}
__device__ __forceinline__ void fma2(u64& d, u64 a, u64 b) {
    asm("fma.rn.f32x2 %0, %1, %2, %0;" : "+l"(d) : "l"(a), "l"(b));
}
__device__ __forceinline__ void unpack2(float& x, float& y, u64 v) {
    asm("mov.b64 {%0, %1}, %2;" : "=f"(x), "=f"(y) : "l"(v));
}
__device__ __forceinline__ unsigned ph2(float a, float b) {
    __half2 h = __floats2half2_rn(a, b); return *(unsigned*)&h;
}
__device__ __forceinline__ float hget(const uint4& q, int ch) {
    unsigned w = (ch < 2) ? q.x : (ch < 4) ? q.y : (ch < 6) ? q.z : q.w;
    __half2 h = *(__half2*)&w;
    return (ch & 1) ? __high2float(h) : __low2float(h);
}
#define H2C(q, k) (*((const __half2*)&(q) + (k)))
#define ACCQ(q) { \
    float2 f0 = __half22float2(H2C(q,0)); \
    float2 f1 = __half22float2(H2C(q,1)); \
    float2 f2 = __half22float2(H2C(q,2)); \
    float2 f3 = __half22float2(H2C(q,3)); \
    a0+=f0.x; a1+=f0.y; a2+=f1.x; a3+=f1.y; \
    a4+=f2.x; a5+=f2.y; a6+=f3.x; a7+=f3.y; }
#define ACC4(q0, q1, q2, q3) { \
    __half2 s0 = __hadd2(__hadd2(H2C(q0,0), H2C(q1,0)), __hadd2(H2C(q2,0), H2C(q3,0))); \
    __half2 s1 = __hadd2(__hadd2(H2C(q0,1), H2C(q1,1)), __hadd2(H2C(q2,1), H2C(q3,1))); \
    __half2 s2 = __hadd2(__hadd2(H2C(q0,2), H2C(q1,2)), __hadd2(H2C(q2,2), H2C(q3,2))); \
    __half2 s3 = __hadd2(__hadd2(H2C(q0,3), H2C(q1,3)), __hadd2(H2C(q2,3), H2C(q3,3))); \
    float2 f0 = __half22float2(s0); float2 f1 = __half22float2(s1); \
    float2 f2 = __half22float2(s2); float2 f3 = __half22float2(s3); \
    a0+=f0.x; a1+=f0.y; a2+=f1.x; a3+=f1.y; \
    a4+=f2.x; a5+=f2.y; a6+=f3.x; a7+=f3.y; }

// ---------------- setup kernels ----------------

__global__ void k_zero() {
    int i = blockIdx.x * blockDim.x + threadIdx.x;
    int stride = gridDim.x * blockDim.x;
    for (int j = i; j < Nn;       j += stride) g_deg[j] = 0;
    for (int j = i; j < Bb * HID; j += stride) g_hg[j]  = 0.f;
    for (int j = i; j < NT;       j += stride) g_tilest[j] = 0u;
    if (i < Bb) g_cnt[i] = 0.f;
    if (i == 0) g_ticket = 0;
}

__global__ void k_deg(const int* __restrict__ dst,
                      const int* __restrict__ graph_ids) {
    int i = blockIdx.x * blockDim.x + threadIdx.x;
    if (i < Ee) g_rank[i] = atomicAdd(&g_deg[dst[i]], 1);
    if (i < Nn) atomicAdd(&g_cnt[graph_ids[i]], 1.0f);
}

__global__ void __launch_bounds__(256) k_scan() {
    __shared__ int s_ticket, s_run;
    __shared__ int ssum[256];
    int tid = threadIdx.x;
    if (tid == 0) s_ticket = atomicAdd(&g_ticket, 1);
    __syncthreads();
    int t = s_ticket;
    int base = t * TILE + tid * 4;
    int d[4]; int s = 0;
    #pragma unroll
    for (int it = 0; it < 4; it++) {
        int idx = base + it;
        d[it] = (idx < Nn) ? g_deg[idx] : 0;
        s += d[it];
    }
    ssum[tid] = s; __syncthreads();
    #pragma unroll
    for (int off = 1; off < 256; off <<= 1) {
        int x = (tid >= off) ? ssum[tid - off] : 0;
        __syncthreads();
        ssum[tid] += x;
        __syncthreads();
    }
    int texcl = ssum[tid] - s;
    int total = ssum[255];
    if (tid == 0) {
        if (t == 0) {
            g_tilest[0] = (2u << 30) | (unsigned)total;
            s_run = 0;
        } else {
            g_tilest[t] = (1u << 30) | (unsigned)total;
            int run = 0, p = t - 1;
            while (true) {
                unsigned w = g_tilest[p];
                unsigned f = w >> 30;
                if (f == 2u) { run += (int)(w & 0x3FFFFFFFu); break; }
                if (f == 1u) { run += (int)(w & 0x3FFFFFFFu); p--; }
            }
            g_tilest[t] = (2u << 30) | (unsigned)(run + total);
            s_run = run;
        }
    }
    __syncthreads();
    int ex = s_run + texcl;
    #pragma unroll
    for (int it = 0; it < 4; it++) {
        int idx = base + it;
        if (idx < Nn) {
            g_rowptr[idx] = ex;
            int dd = d[it];
            g_dinv[idx] = (dd > 0) ? 1.0f / (float)dd : 0.0f;
            ex += dd;
        }
    }
}

__global__ void k_fill_gather(const int* __restrict__ src, const int* __restrict__ dst,
                              const int* __restrict__ node_ids,
                              const float4* __restrict__ emb) {
    int i = blockIdx.x * blockDim.x + threadIdx.x;
    if (i < Ee) {
        int d = dst[i];
        g_csr[g_rowptr[d] + g_rank[i]] = src[i];
    }
    if (i < Nn * 4) {
        int n = i >> 2, c = i & 3;
        float4 v0 = emb[node_ids[n] * 8 + c * 2 + 0];
        float4 v1 = emb[node_ids[n] * 8 + c * 2 + 1];
        uint4 o;
        o.x = ph2(v0.x, v0.y); o.y = ph2(v0.z, v0.w);
        o.z = ph2(v1.x, v1.y); o.w = ph2(v1.z, v1.w);
        g_h0h[n * 4 + c] = o;
    }
}

// ---------------- fused layer 1: agg (smem) + update ----------------

__global__ void __launch_bounds__(NPB)
k_layer1(const float* __restrict__ Wse, const float* __restrict__ Wne,
         const float* __restrict__ b) {
    extern __shared__ char smem[];
    float* sW  = (float*)smem;               // 2*EMB*HID floats (16 KB)
    float* sb  = sW + 2 * EMB * HID;         // HID floats
    uint4* sh_h  = (uint4*)(sb + HID);       // NPB*4 (16 KB)
    uint4* sh_ag = sh_h + NPB * 4;           // NPB*4 (16 KB)

    int tid  = threadIdx.x;
    int base = blockIdx.x * NPB;
    int nb   = min(NPB, Nn - base);

    for (int i = tid; i < EMB * HID; i += NPB) { sW[i] = Wse[i]; sW[EMB*HID + i] = Wne[i]; }
    if (tid < HID) sb[tid] = b[tid];
    for (int i = tid; i < nb * 4; i += NPB) sh_h[i] = g_h0h[base * 4 + i];
    __syncthreads();

    // phase B: aggregate neighbors (global) into smem
    for (int task = tid; task < nb * 4; task += NPB) {
        int nl = task >> 2, c = task & 3;
        int n = base + nl;
        int beg = g_rowptr[n], cnt = g_deg[n];
        float a0=0.f,a1=0.f,a2=0.f,a3=0.f,a4=0.f,a5=0.f,a6=0.f,a7=0.f;
        int i = 0;
        for (; i + 7 < cnt; i += 8) {
            int s0 = __ldg(&g_csr[beg+i+0]), s1 = __ldg(&g_csr[beg+i+1]);
            int s2 = __ldg(&g_csr[beg+i+2]), s3 = __ldg(&g_csr[beg+i+3]);
            int s4 = __ldg(&g_csr[beg+i+4]), s5 = __ldg(&g_csr[beg+i+5]);
            int s6 = __ldg(&g_csr[beg+i+6]), s7 = __ldg(&g_csr[beg+i+7]);
            uint4 q0 = g_h0h[s0*4+c], q1 = g_h0h[s1*4+c];
            uint4 q2 = g_h0h[s2*4+c], q3 = g_h0h[s3*4+c];
            uint4 q4 = g_h0h[s4*4+c], q5 = g_h0h[s5*4+c];
            uint4 q6 = g_h0h[s6*4+c], q7 = g_h0h[s7*4+c];
            ACC4(q0, q1, q2, q3)
            ACC4(q4, q5, q6, q7)
        }
        for (; i + 3 < cnt; i += 4) {
            int s0 = __ldg(&g_csr[beg+i+0]), s1 = __ldg(&g_csr[beg+i+1]);
            int s2 = __ldg(&g_csr[beg+i+2]), s3 = __ldg(&g_csr[beg+i+3]);
            uint4 q0 = g_h0h[s0*4+c], q1 = g_h0h[s1*4+c];
            uint4 q2 = g_h0h[s2*4+c], q3 = g_h0h[s3*4+c];
            ACC4(q0, q1, q2, q3)
        }
        for (; i < cnt; i++) {
            int s = __ldg(&g_csr[beg+i]);
            uint4 q = g_h0h[s*4+c];
            ACCQ(q)
        }
        float dinv = g_dinv[n];
        uint4 o;
        o.x = ph2(a0*dinv, a1*dinv); o.y = ph2(a2*dinv, a3*dinv);
        o.z = ph2(a4*dinv, a5*dinv); o.w = ph2(a6*dinv, a7*dinv);
        sh_ag[task] = o;
    }
    __syncthreads();

    // phase C: dense update, all operands from smem
    if (tid < nb) {
        int n = base + tid;
        #pragma unroll 1
        for (int q = 0; q < 4; q++) {
            u64 acc[8];
            #pragma unroll
            for (int j2 = 0; j2 < 8; j2++)
                acc[j2] = pack2(sb[q*16 + 2*j2], sb[q*16 + 2*j2 + 1]);
            #pragma unroll 1
            for (int kk = 0; kk < 4; kk++) {
                uint4 hq = sh_h[tid*4 + kk];
                uint4 aq = sh_ag[tid*4 + kk];
                #pragma unroll
                for (int ch = 0; ch < 8; ch++) {
                    int k = kk*8 + ch;
                    const ulonglong2* ws = (const ulonglong2*)&sW[k * HID + q*16];
                    const ulonglong2* wn = (const ulonglong2*)&sW[(EMB + k) * HID + q*16];
                    float hf = hget(hq, ch), af = hget(aq, ch);
                    u64 bh = pack2(hf, hf), ba = pack2(af, af);
                    #pragma unroll
                    for (int j4 = 0; j4 < 4; j4++) {
                        ulonglong2 w = ws[j4], v = wn[j4];
                        fma2(acc[j4*2+0], bh, w.x); fma2(acc[j4*2+1], bh, w.y);
                        fma2(acc[j4*2+0], ba, v.x); fma2(acc[j4*2+1], ba, v.y);
                    }
                }
            }
            #pragma unroll
            for (int half = 0; half < 2; half++) {
                float x0,x1,x2,x3,x4,x5,x6,x7;
                unpack2(x0,x1, acc[half*4+0]); unpack2(x2,x3, acc[half*4+1]);
                unpack2(x4,x5, acc[half*4+2]); unpack2(x6,x7, acc[half*4+3]);
                uint4 o;
                o.x = ph2(fmaxf(x0,0.f), fmaxf(x1,0.f));
                o.y = ph2(fmaxf(x2,0.f), fmaxf(x3,0.f));
                o.z = ph2(fmaxf(x4,0.f), fmaxf(x5,0.f));
                o.w = ph2(fmaxf(x6,0.f), fmaxf(x7,0.f));
                g_h1h[n*8 + q*2 + half] = o;
            }
        }
    }
}

// ---------------- fused layer 2: agg (smem) + update + pooling ----------------

__global__ void __launch_bounds__(NPB)
k_layer2(const float* __restrict__ Wse, const float* __restrict__ Wne,
         const float* __restrict__ b, const int* __restrict__ graph_ids) {
    extern __shared__ char smem[];
    float* sW  = (float*)smem;               // 2*HID*HID floats (32 KB)
    float* sb  = sW + 2 * HID * HID;         // HID floats
    uint4* sh_h  = (uint4*)(sb + HID);       // NPB*8 (32 KB)
    uint4* sh_ag = sh_h + NPB * 8;           // NPB*8 (32 KB)

    int tid  = threadIdx.x;
    int base = blockIdx.x * NPB;
    int nb   = min(NPB, Nn - base);

    for (int i = tid; i < HID * HID; i += NPB) { sW[i] = Wse[i]; sW[HID*HID + i] = Wne[i]; }
    if (tid < HID) sb[tid] = b[tid];
    for (int i = tid; i < nb * 8; i += NPB) sh_h[i] = g_h1h[base * 8 + i];
    __syncthreads();

    // phase B: aggregate neighbors into smem
    for (int task = tid; task < nb * 8; task += NPB) {
        int nl = task >> 3, c = task & 7;
        int n = base + nl;
        int beg = g_rowptr[n], cnt = g_deg[n];
        float a0=0.f,a1=0.f,a2=0.f,a3=0.f,a4=0.f,a5=0.f,a6=0.f,a7=0.f;
        int i = 0;
        for (; i + 7 < cnt; i += 8) {
            int s0 = __ldg(&g_csr[beg+i+0]), s1 = __ldg(&g_csr[beg+i+1]);
            int s2 = __ldg(&g_csr[beg+i+2]), s3 = __ldg(&g_csr[beg+i+3]);
            int s4 = __ldg(&g_csr[beg+i+4]), s5 = __ldg(&g_csr[beg+i+5]);
            int s6 = __ldg(&g_csr[beg+i+6]), s7 = __ldg(&g_csr[beg+i+7]);
            uint4 q0 = g_h1h[s0*8+c], q1 = g_h1h[s1*8+c];
            uint4 q2 = g_h1h[s2*8+c], q3 = g_h1h[s3*8+c];
            uint4 q4 = g_h1h[s4*8+c], q5 = g_h1h[s5*8+c];
            uint4 q6 = g_h1h[s6*8+c], q7 = g_h1h[s7*8+c];
            ACC4(q0, q1, q2, q3)
            ACC4(q4, q5, q6, q7)
        }
        for (; i + 3 < cnt; i += 4) {
            int s0 = __ldg(&g_csr[beg+i+0]), s1 = __ldg(&g_csr[beg+i+1]);
            int s2 = __ldg(&g_csr[beg+i+2]), s3 = __ldg(&g_csr[beg+i+3]);
            uint4 q0 = g_h1h[s0*8+c], q1 = g_h1h[s1*8+c];
            uint4 q2 = g_h1h[s2*8+c], q3 = g_h1h[s3*8+c];
            ACC4(q0, q1, q2, q3)
        }
        for (; i < cnt; i++) {
            int s = __ldg(&g_csr[beg+i]);
            uint4 q = g_h1h[s*8+c];
            ACCQ(q)
        }
        float dinv = g_dinv[n];
        uint4 o;
        o.x = ph2(a0*dinv, a1*dinv); o.y = ph2(a2*dinv, a3*dinv);
        o.z = ph2(a4*dinv, a5*dinv); o.w = ph2(a6*dinv, a7*dinv);
        sh_ag[task] = o;
    }
    __syncthreads();

    // phase C: dense update + pooling, operands from smem
    if (tid < nb) {
        int n = base + tid;
        int g = graph_ids[n];
        float4* hgv = (float4*)&g_hg[g * HID];
        #pragma unroll 1
        for (int q = 0; q < 4; q++) {
            u64 acc[8];
            #pragma unroll
            for (int j2 = 0; j2 < 8; j2++)
                acc[j2] = pack2(sb[q*16 + 2*j2], sb[q*16 + 2*j2 + 1]);
            #pragma unroll 1
            for (int kk = 0; kk < 8; kk++) {
                uint4 hq = sh_h[tid*8 + kk];
                uint4 aq = sh_ag[tid*8 + kk];
                #pragma unroll
                for (int ch = 0; ch < 8; ch++) {
                    int k = kk*8 + ch;
                    const ulonglong2* ws = (const ulonglong2*)&sW[k * HID + q*16];
                    const ulonglong2* wn = (const ulonglong2*)&sW[(HID + k) * HID + q*16];
                    float hf = hget(hq, ch), af = hget(aq, ch);
                    u64 bh = pack2(hf, hf), ba = pack2(af, af);
                    #pragma unroll
                    for (int j4 = 0; j4 < 4; j4++) {
                        ulonglong2 w = ws[j4], v = wn[j4];
                        fma2(acc[j4*2+0], bh, w.x); fma2(acc[j4*2+1], bh, w.y);
                        fma2(acc[j4*2+0], ba, v.x); fma2(acc[j4*2+1], ba, v.y);
                    }
                }
            }
            #pragma unroll
            for (int j4 = 0; j4 < 4; j4++) {
                float x0,x1,x2,x3;
                unpack2(x0, x1, acc[j4*2+0]);
                unpack2(x2, x3, acc[j4*2+1]);
                red4(&hgv[q*4 + j4], make_float4(fmaxf(x0,0.f), fmaxf(x1,0.f),
                                                 fmaxf(x2,0.f), fmaxf(x3,0.f)));
            }
        }
    }
}

// scorer
__global__ void k_final(const float* __restrict__ Ws1, const float* __restrict__ bs1,
                        const float* __restrict__ Ws2, const float* __restrict__ bs2,
                        float* __restrict__ out) {
    __shared__ float sW[HID * HID];
    int tid = threadIdx.x;
    for (int i = tid; i < HID * HID; i += 64) sW[i] = Ws1[i];
    __syncthreads();

    int g = blockIdx.x * 64 + tid;
    if (g >= Bb) return;

    float inv = 1.0f / fmaxf(g_cnt[g], 1.0f);
    float hv[HID];
    #pragma unroll
    for (int k = 0; k < HID; k++) hv[k] = g_hg[g * HID + k] * inv;

    float s = bs2[0];
    #pragma unroll 1
    for (int j = 0; j < HID; j++) {
        float t = bs1[j];
        #pragma unroll
        for (int k = 0; k < HID; k++) t += hv[k] * sW[k * HID + j];
        s += fmaxf(t, 0.f) * Ws2[j];
    }
    out[g] = s;
}

// ---------------- launcher ----------------
extern "C" void kernel_launch(void* const* d_in, const int* in_sizes, int n_in,
                              void* d_out, int out_size) {
    const int*    node_ids  = (const int*)   d_in[0];
    const int*    src       = (const int*)   d_in[1];
    const int*    dst       = (const int*)   d_in[2];
    const int*    graph_ids = (const int*)   d_in[3];
    const float4* emb       = (const float4*)d_in[4];
    const float*  W_self1   = (const float*) d_in[5];
    const float*  W_neigh1  = (const float*) d_in[6];
    const float*  b1        = (const float*) d_in[7];
    const float*  W_self2   = (const float*) d_in[8];
    const float*  W_neigh2  = (const float*) d_in[9];
    const float*  b2        = (const float*) d_in[10];
    const float*  Ws1       = (const float*) d_in[11];
    const float*  bs1       = (const float*) d_in[12];
    const float*  Ws2       = (const float*) d_in[13];
    const float*  bs2       = (const float*) d_in[14];
    float* out = (float*)d_out;

    cudaFuncSetAttribute(k_layer1, cudaFuncAttributeMaxDynamicSharedMemorySize, SMEM1);
    cudaFuncSetAttribute(k_layer2, cudaFuncAttributeMaxDynamicSharedMemorySize, SMEM2);

    k_zero       <<<512, 256>>>();                                      // 0
    k_deg        <<<(Ee + 255) / 256, 256>>>(dst, graph_ids);           // 1
    k_scan       <<<NT, 256>>>();                                       // 2
    k_fill_gather<<<(Ee + 255) / 256, 256>>>(src, dst, node_ids, emb);  // 3
    k_layer1     <<<NBLK, NPB, SMEM1>>>(W_self1, W_neigh1, b1);         // 4
    k_layer2     <<<NBLK, NPB, SMEM2>>>(W_self2, W_neigh2, b2, graph_ids); // 5
    k_final      <<<(Bb + 63) / 64, 64>>>(Ws1, bs1, Ws2, bs2, out);     // 6
}

// round 12
// speedup vs baseline: 1.1472x; 1.1472x over previous
#include <cuda_runtime.h>
#include <cuda_fp16.h>

typedef unsigned long long u64;

#define Nn   200000
#define Ee   3200000
#define Bb   512
#define EMB  32
#define HID  64
#define TILE 1024
#define NT   ((Nn + TILE - 1) / TILE)   // 196 scan tiles

// ---------------- scratch (device globals) ----------------
__device__ uint4 g_h0h [Nn * 4];          // 12.8 MB fp16 h0
__device__ uint4 g_ag1h[Nn * 4];          // 12.8 MB fp16 agg1
__device__ uint4 g_h1h [Nn * 8];          // 25.6 MB fp16 h1
__device__ uint4 g_ag2h[Nn * 8];          // 25.6 MB fp16 agg2
__device__ int   g_csr [Ee];              // 12.8 MB
__device__ int   g_rank[Ee];              // 12.8 MB edge rank within dst
__device__ int   g_rowptr[Nn];
__device__ int   g_deg [Nn];
__device__ float g_dinv[Nn];
__device__ float g_hg  [Bb * HID];
__device__ float g_cnt [Bb];
__device__ volatile unsigned g_tilest[NT];
__device__ int   g_ticket;

// ---------------- helpers ----------------
__device__ __forceinline__ void red4(float4* p, float4 v) {
    asm volatile("red.global.add.v4.f32 [%0], {%1,%2,%3,%4};"
                 :: "l"(p), "f"(v.x), "f"(v.y), "f"(v.z), "f"(v.w) : "memory");
}
__device__ __forceinline__ u64 pack2(float x, float y) {
    u64 r; asm("mov.b64 %0, {%1, %2};" : "=l"(r) : "f"(x), "f"(y)); return r;
}
__device__ __forceinline__ void fma2(u64& d, u64 a, u64 b) {
    asm("fma.rn.f32x2 %0, %1, %2, %0;" : "+l"(d) : "l"(a), "l"(b));
}
__device__ __forceinline__ void unpack2(float& x, float& y, u64 v) {
    asm("mov.b64 {%0, %1}, %2;" : "=f"(x), "=f"(y) : "l"(v));
}
__device__ __forceinline__ unsigned ph2(float a, float b) {
    __half2 h = __floats2half2_rn(a, b); return *(unsigned*)&h;
}
__device__ __forceinline__ float hget(const uint4& q, int ch) {
    unsigned w = (ch < 2) ? q.x : (ch < 4) ? q.y : (ch < 6) ? q.z : q.w;
    __half2 h = *(__half2*)&w;
    return (ch & 1) ? __high2float(h) : __low2float(h);
}
#define H2C(q, k) (*((const __half2*)&(q) + (k)))
#define ACCQ(q) { \
    float2 f0 = __half22float2(H2C(q,0)); \
    float2 f1 = __half22float2(H2C(q,1)); \
    float2 f2 = __half22float2(H2C(q,2)); \
    float2 f3 = __half22float2(H2C(q,3)); \
    a0+=f0.x; a1+=f0.y; a2+=f1.x; a3+=f1.y; \
    a4+=f2.x; a5+=f2.y; a6+=f3.x; a7+=f3.y; }
#define ACC4(q0, q1, q2, q3) { \
    __half2 s0 = __hadd2(__hadd2(H2C(q0,0), H2C(q1,0)), __hadd2(H2C(q2,0), H2C(q3,0))); \
    __half2 s1 = __hadd2(__hadd2(H2C(q0,1), H2C(q1,1)), __hadd2(H2C(q2,1), H2C(q3,1))); \
    __half2 s2 = __hadd2(__hadd2(H2C(q0,2), H2C(q1,2)), __hadd2(H2C(q2,2), H2C(q3,2))); \
    __half2 s3 = __hadd2(__hadd2(H2C(q0,3), H2C(q1,3)), __hadd2(H2C(q2,3), H2C(q3,3))); \
    float2 f0 = __half22float2(s0); float2 f1 = __half22float2(s1); \
    float2 f2 = __half22float2(s2); float2 f3 = __half22float2(s3); \
    a0+=f0.x; a1+=f0.y; a2+=f1.x; a3+=f1.y; \
    a4+=f2.x; a5+=f2.y; a6+=f3.x; a7+=f3.y; }

// ---------------- setup kernels ----------------

__global__ void k_zero() {
    int i = blockIdx.x * blockDim.x + threadIdx.x;
    int stride = gridDim.x * blockDim.x;
    for (int j = i; j < Nn;       j += stride) g_deg[j] = 0;
    for (int j = i; j < Bb * HID; j += stride) g_hg[j]  = 0.f;
    for (int j = i; j < NT;       j += stride) g_tilest[j] = 0u;
    if (i < Bb) g_cnt[i] = 0.f;
    if (i == 0) g_ticket = 0;
}

__global__ void k_deg(const int* __restrict__ dst,
                      const int* __restrict__ graph_ids) {
    int i = blockIdx.x * blockDim.x + threadIdx.x;
    if (i < Ee) g_rank[i] = atomicAdd(&g_deg[dst[i]], 1);
    if (i < Nn) atomicAdd(&g_cnt[graph_ids[i]], 1.0f);
}

__global__ void __launch_bounds__(256) k_scan() {
    __shared__ int s_ticket, s_run;
    __shared__ int ssum[256];
    int tid = threadIdx.x;
    if (tid == 0) s_ticket = atomicAdd(&g_ticket, 1);
    __syncthreads();
    int t = s_ticket;
    int base = t * TILE + tid * 4;
    int d[4]; int s = 0;
    #pragma unroll
    for (int it = 0; it < 4; it++) {
        int idx = base + it;
        d[it] = (idx < Nn) ? g_deg[idx] : 0;
        s += d[it];
    }
    ssum[tid] = s; __syncthreads();
    #pragma unroll
    for (int off = 1; off < 256; off <<= 1) {
        int x = (tid >= off) ? ssum[tid - off] : 0;
        __syncthreads();
        ssum[tid] += x;
        __syncthreads();
    }
    int texcl = ssum[tid] - s;
    int total = ssum[255];
    if (tid == 0) {
        if (t == 0) {
            g_tilest[0] = (2u << 30) | (unsigned)total;
            s_run = 0;
        } else {
            g_tilest[t] = (1u << 30) | (unsigned)total;
            int run = 0, p = t - 1;
            while (true) {
                unsigned w = g_tilest[p];
                unsigned f = w >> 30;
                if (f == 2u) { run += (int)(w & 0x3FFFFFFFu); break; }
                if (f == 1u) { run += (int)(w & 0x3FFFFFFFu); p--; }
            }
            g_tilest[t] = (2u << 30) | (unsigned)(run + total);
            s_run = run;
        }
    }
    __syncthreads();
    int ex = s_run + texcl;
    #pragma unroll
    for (int it = 0; it < 4; it++) {
        int idx = base + it;
        if (idx < Nn) {
            g_rowptr[idx] = ex;
            int dd = d[it];
            g_dinv[idx] = (dd > 0) ? 1.0f / (float)dd : 0.0f;
            ex += dd;
        }
    }
}

__global__ void k_fill_gather(const int* __restrict__ src, const int* __restrict__ dst,
                              const int* __restrict__ node_ids,
                              const float4* __restrict__ emb) {
    int i = blockIdx.x * blockDim.x + threadIdx.x;
    if (i < Ee) {
        int d = dst[i];
        g_csr[g_rowptr[d] + g_rank[i]] = src[i];
    }
    if (i < Nn * 4) {
        int n = i >> 2, c = i & 3;
        float4 v0 = emb[node_ids[n] * 8 + c * 2 + 0];
        float4 v1 = emb[node_ids[n] * 8 + c * 2 + 1];
        uint4 o;
        o.x = ph2(v0.x, v0.y); o.y = ph2(v0.z, v0.w);
        o.z = ph2(v1.x, v1.y); o.w = ph2(v1.z, v1.w);
        g_h0h[n * 4 + c] = o;
    }
}

// ---------------- aggregation (pairwise fp16, fp32 outer) ----------------

__global__ void k_agg1() {
    int t = blockIdx.x * blockDim.x + threadIdx.x;
    if (t >= Nn * 4) return;
    int n = t >> 2, c = t & 3;
    int beg = g_rowptr[n], cnt = g_deg[n];
    float a0=0.f,a1=0.f,a2=0.f,a3=0.f,a4=0.f,a5=0.f,a6=0.f,a7=0.f;
    int i = 0;
    for (; i + 7 < cnt; i += 8) {
        int s0 = __ldg(&g_csr[beg+i+0]), s1 = __ldg(&g_csr[beg+i+1]);
        int s2 = __ldg(&g_csr[beg+i+2]), s3 = __ldg(&g_csr[beg+i+3]);
        int s4 = __ldg(&g_csr[beg+i+4]), s5 = __ldg(&g_csr[beg+i+5]);
        int s6 = __ldg(&g_csr[beg+i+6]), s7 = __ldg(&g_csr[beg+i+7]);
        uint4 q0 = g_h0h[s0*4+c], q1 = g_h0h[s1*4+c];
        uint4 q2 = g_h0h[s2*4+c], q3 = g_h0h[s3*4+c];
        uint4 q4 = g_h0h[s4*4+c], q5 = g_h0h[s5*4+c];
        uint4 q6 = g_h0h[s6*4+c], q7 = g_h0h[s7*4+c];
        ACC4(q0, q1, q2, q3)
        ACC4(q4, q5, q6, q7)
    }
    for (; i + 3 < cnt; i += 4) {
        int s0 = __ldg(&g_csr[beg+i+0]), s1 = __ldg(&g_csr[beg+i+1]);
        int s2 = __ldg(&g_csr[beg+i+2]), s3 = __ldg(&g_csr[beg+i+3]);
        uint4 q0 = g_h0h[s0*4+c], q1 = g_h0h[s1*4+c];
        uint4 q2 = g_h0h[s2*4+c], q3 = g_h0h[s3*4+c];
        ACC4(q0, q1, q2, q3)
    }
    for (; i < cnt; i++) {
        int s = __ldg(&g_csr[beg+i]);
        uint4 q = g_h0h[s*4+c];
        ACCQ(q)
    }
    float dinv = g_dinv[n];
    uint4 o;
    o.x = ph2(a0*dinv, a1*dinv); o.y = ph2(a2*dinv, a3*dinv);
    o.z = ph2(a4*dinv, a5*dinv); o.w = ph2(a6*dinv, a7*dinv);
    g_ag1h[n*4 + c] = o;
}

__global__ void k_agg2() {
    int t = blockIdx.x * blockDim.x + threadIdx.x;
    if (t >= Nn * 8) return;
    int n = t >> 3, c = t & 7;
    int beg = g_rowptr[n], cnt = g_deg[n];
    float a0=0.f,a1=0.f,a2=0.f,a3=0.f,a4=0.f,a5=0.f,a6=0.f,a7=0.f;
    int i = 0;
    for (; i + 7 < cnt; i += 8) {
        int s0 = __ldg(&g_csr[beg+i+0]), s1 = __ldg(&g_csr[beg+i+1]);
        int s2 = __ldg(&g_csr[beg+i+2]), s3 = __ldg(&g_csr[beg+i+3]);
        int s4 = __ldg(&g_csr[beg+i+4]), s5 = __ldg(&g_csr[beg+i+5]);
        int s6 = __ldg(&g_csr[beg+i+6]), s7 = __ldg(&g_csr[beg+i+7]);
        uint4 q0 = g_h1h[s0*8+c], q1 = g_h1h[s1*8+c];
        uint4 q2 = g_h1h[s2*8+c], q3 = g_h1h[s3*8+c];
        uint4 q4 = g_h1h[s4*8+c], q5 = g_h1h[s5*8+c];
        uint4 q6 = g_h1h[s6*8+c], q7 = g_h1h[s7*8+c];
        ACC4(q0, q1, q2, q3)
        ACC4(q4, q5, q6, q7)
    }
    for (; i + 3 < cnt; i += 4) {
        int s0 = __ldg(&g_csr[beg+i+0]), s1 = __ldg(&g_csr[beg+i+1]);
        int s2 = __ldg(&g_csr[beg+i+2]), s3 = __ldg(&g_csr[beg+i+3]);
        uint4 q0 = g_h1h[s0*8+c], q1 = g_h1h[s1*8+c];
        uint4 q2 = g_h1h[s2*8+c], q3 = g_h1h[s3*8+c];
        ACC4(q0, q1, q2, q3)
    }
    for (; i < cnt; i++) {
        int s = __ldg(&g_csr[beg+i]);
        uint4 q = g_h1h[s*8+c];
        ACCQ(q)
    }
    float dinv = g_dinv[n];
    uint4 o;
    o.x = ph2(a0*dinv, a1*dinv); o.y = ph2(a2*dinv, a3*dinv);
    o.z = ph2(a4*dinv, a5*dinv); o.w = ph2(a6*dinv, a7*dinv);
    g_ag2h[n*8 + c] = o;
}

// ---------------- dense updates: 1 node/thread, quarter-split, LDS.128 weights ------

__global__ void __launch_bounds__(256)
k_update1(const float* __restrict__ Wse, const float* __restrict__ Wne,
          const float* __restrict__ b) {
    __shared__ float sW[2 * EMB * HID];   // 16 KB
    __shared__ float sb[HID];
    int tid = threadIdx.x;
    for (int i = tid; i < EMB * HID; i += 256) { sW[i] = Wse[i]; sW[EMB*HID + i] = Wne[i]; }
    if (tid < HID) sb[tid] = b[tid];
    __syncthreads();

    int n = blockIdx.x * 256 + tid;
    if (n >= Nn) return;

    #pragma unroll 1
    for (int q = 0; q < 4; q++) {     // quarter = 16 output cols
        u64 acc[8];
        #pragma unroll
        for (int j2 = 0; j2 < 8; j2++)
            acc[j2] = pack2(sb[q*16 + 2*j2], sb[q*16 + 2*j2 + 1]);
        #pragma unroll 1
        for (int kk = 0; kk < 4; kk++) {
            uint4 hq = g_h0h[n*4 + kk];
            uint4 aq = g_ag1h[n*4 + kk];
            #pragma unroll
            for (int ch = 0; ch < 8; ch++) {
                int k = kk*8 + ch;
                const ulonglong2* ws = (const ulonglong2*)&sW[k * HID + q*16];
                const ulonglong2* wn = (const ulonglong2*)&sW[(EMB + k) * HID + q*16];
                float hf = hget(hq, ch), af = hget(aq, ch);
                u64 bh = pack2(hf, hf), ba = pack2(af, af);
                #pragma unroll
                for (int j4 = 0; j4 < 4; j4++) {
                    ulonglong2 w = ws[j4], v = wn[j4];
                    fma2(acc[j4*2+0], bh, w.x); fma2(acc[j4*2+1], bh, w.y);
                    fma2(acc[j4*2+0], ba, v.x); fma2(acc[j4*2+1], ba, v.y);
                }
            }
        }
        #pragma unroll
        for (int half = 0; half < 2; half++) {
            float x0,x1,x2,x3,x4,x5,x6,x7;
            unpack2(x0,x1, acc[half*4+0]); unpack2(x2,x3, acc[half*4+1]);
            unpack2(x4,x5, acc[half*4+2]); unpack2(x6,x7, acc[half*4+3]);
            uint4 o;
            o.x = ph2(fmaxf(x0,0.f), fmaxf(x1,0.f));
            o.y = ph2(fmaxf(x2,0.f), fmaxf(x3,0.f));
            o.z = ph2(fmaxf(x4,0.f), fmaxf(x5,0.f));
            o.w = ph2(fmaxf(x6,0.f), fmaxf(x7,0.f));
            g_h1h[n*8 + q*2 + half] = o;
        }
    }
}

__global__ void __launch_bounds__(256)
k_update2(const float* __restrict__ Wse, const float* __restrict__ Wne,
          const float* __restrict__ b, const int* __restrict__ graph_ids) {
    __shared__ float sW[2 * HID * HID];   // 32 KB
    __shared__ float sb[HID];
    int tid = threadIdx.x;
    for (int i = tid; i < HID * HID; i += 256) { sW[i] = Wse[i]; sW[HID*HID + i] = Wne[i]; }
    if (tid < HID) sb[tid] = b[tid];
    __syncthreads();

    int n = blockIdx.x * 256 + tid;
    if (n >= Nn) return;
    int g = graph_ids[n];
    float4* hgv = (float4*)&g_hg[g * HID];

    #pragma unroll 1
    for (int q = 0; q < 4; q++) {
        u64 acc[8];
        #pragma unroll
        for (int j2 = 0; j2 < 8; j2++)
            acc[j2] = pack2(sb[q*16 + 2*j2], sb[q*16 + 2*j2 + 1]);
        #pragma unroll 1
        for (int kk = 0; kk < 8; kk++) {
            uint4 hq = g_h1h[n*8 + kk];
            uint4 aq = g_ag2h[n*8 + kk];
            #pragma unroll
            for (int ch = 0; ch < 8; ch++) {
                int k = kk*8 + ch;
                const ulonglong2* ws = (const ulonglong2*)&sW[k * HID + q*16];
                const ulonglong2* wn = (const ulonglong2*)&sW[(HID + k) * HID + q*16];
                float hf = hget(hq, ch), af = hget(aq, ch);
                u64 bh = pack2(hf, hf), ba = pack2(af, af);
                #pragma unroll
                for (int j4 = 0; j4 < 4; j4++) {
                    ulonglong2 w = ws[j4], v = wn[j4];
                    fma2(acc[j4*2+0], bh, w.x); fma2(acc[j4*2+1], bh, w.y);
                    fma2(acc[j4*2+0], ba, v.x); fma2(acc[j4*2+1], ba, v.y);
                }
            }
        }
        #pragma unroll
        for (int j4 = 0; j4 < 4; j4++) {
            float x0,x1,x2,x3;
            unpack2(x0, x1, acc[j4*2+0]);
            unpack2(x2, x3, acc[j4*2+1]);
            red4(&hgv[q*4 + j4], make_float4(fmaxf(x0,0.f), fmaxf(x1,0.f),
                                             fmaxf(x2,0.f), fmaxf(x3,0.f)));
        }
    }
}

// scorer
__global__ void k_final(const float* __restrict__ Ws1, const float* __restrict__ bs1,
                        const float* __restrict__ Ws2, const float* __restrict__ bs2,
                        float* __restrict__ out) {
    __shared__ float sW[HID * HID];
    int tid = threadIdx.x;
    for (int i = tid; i < HID * HID; i += 64) sW[i] = Ws1[i];
    __syncthreads();

    int g = blockIdx.x * 64 + tid;
    if (g >= Bb) return;

    float inv = 1.0f / fmaxf(g_cnt[g], 1.0f);
    float hv[HID];
    #pragma unroll
    for (int k = 0; k < HID; k++) hv[k] = g_hg[g * HID + k] * inv;

    float s = bs2[0];
    #pragma unroll 1
    for (int j = 0; j < HID; j++) {
        float t = bs1[j];
        #pragma unroll
        for (int k = 0; k < HID; k++) t += hv[k] * sW[k * HID + j];
        s += fmaxf(t, 0.f) * Ws2[j];
    }
    out[g] = s;
}

// ---------------- launcher ----------------
extern "C" void kernel_launch(void* const* d_in, const int* in_sizes, int n_in,
                              void* d_out, int out_size) {
    const int*    node_ids  = (const int*)   d_in[0];
    const int*    src       = (const int*)   d_in[1];
    const int*    dst       = (const int*)   d_in[2];
    const int*    graph_ids = (const int*)   d_in[3];
    const float4* emb       = (const float4*)d_in[4];
    const float*  W_self1   = (const float*) d_in[5];
    const float*  W_neigh1  = (const float*) d_in[6];
    const float*  b1        = (const float*) d_in[7];
    const float*  W_self2   = (const float*) d_in[8];
    const float*  W_neigh2  = (const float*) d_in[9];
    const float*  b2        = (const float*) d_in[10];
    const float*  Ws1       = (const float*) d_in[11];
    const float*  bs1       = (const float*) d_in[12];
    const float*  Ws2       = (const float*) d_in[13];
    const float*  bs2       = (const float*) d_in[14];
    float* out = (float*)d_out;

    k_zero       <<<512, 256>>>();                                      // 0
    k_deg        <<<(Ee + 255) / 256, 256>>>(dst, graph_ids);           // 1
    k_scan       <<<NT, 256>>>();                                       // 2
    k_fill_gather<<<(Ee + 255) / 256, 256>>>(src, dst, node_ids, emb);  // 3
    k_agg1       <<<(Nn * 4 + 255) / 256, 256>>>();                     // 4
    k_update1    <<<(Nn + 255) / 256, 256>>>(W_self1, W_neigh1, b1);    // 5
    k_agg2       <<<(Nn * 8 + 255) / 256, 256>>>();                     // 6
    k_update2    <<<(Nn + 255) / 256, 256>>>(W_self2, W_neigh2, b2, graph_ids); // 7
    k_final      <<<(Bb + 63) / 64, 64>>>(Ws1, bs1, Ws2, bs2, out);     // 8
}

// round 13
// speedup vs baseline: 1.4352x; 1.2511x over previous
#include <cuda_runtime.h>
#include <cuda_fp16.h>

typedef unsigned long long u64;

#define Nn   200000
#define Ee   3200000
#define Bb   512
#define EMB  32
#define HID  64
#define TILE 1024
#define NT   ((Nn + TILE - 1) / TILE)   // 196 scan tiles

// ---------------- scratch (device globals) ----------------
__device__ uint4 g_h0h [Nn * 4];          // 12.8 MB fp16 h0
__device__ uint4 g_ag1h[Nn * 4];          // 12.8 MB fp16 agg1
__device__ uint4 g_h1h [Nn * 8];          // 25.6 MB fp16 h1
__device__ uint4 g_ag2h[Nn * 8];          // 25.6 MB fp16 agg2
__device__ int   g_csr [Ee];              // 12.8 MB
__device__ int   g_rank[Ee];              // 12.8 MB edge rank within dst
__device__ int   g_rowptr[Nn];
__device__ int   g_deg [Nn];
__device__ float g_dinv[Nn];
__device__ float g_hg  [Bb * HID];
__device__ int   g_gfirst[Bb];
__device__ int   g_glast [Bb];
__device__ volatile unsigned g_tilest[NT];
__device__ int   g_ticket;

// ---------------- helpers ----------------
__device__ __forceinline__ void red4(float4* p, float4 v) {
    asm volatile("red.global.add.v4.f32 [%0], {%1,%2,%3,%4};"
                 :: "l"(p), "f"(v.x), "f"(v.y), "f"(v.z), "f"(v.w) : "memory");
}
__device__ __forceinline__ u64 pack2(float x, float y) {
    u64 r; asm("mov.b64 %0, {%1, %2};" : "=l"(r) : "f"(x), "f"(y)); return r;
}
__device__ __forceinline__ void fma2(u64& d, u64 a, u64 b) {
    asm("fma.rn.f32x2 %0, %1, %2, %0;" : "+l"(d) : "l"(a), "l"(b));
}
__device__ __forceinline__ void unpack2(float& x, float& y, u64 v) {
    asm("mov.b64 {%0, %1}, %2;" : "=f"(x), "=f"(y) : "l"(v));
}
__device__ __forceinline__ unsigned ph2(float a, float b) {
    __half2 h = __floats2half2_rn(a, b); return *(unsigned*)&h;
}
__device__ __forceinline__ float hget(const uint4& q, int ch) {
    unsigned w = (ch < 2) ? q.x : (ch < 4) ? q.y : (ch < 6) ? q.z : q.w;
    __half2 h = *(__half2*)&w;
    return (ch & 1) ? __high2float(h) : __low2float(h);
}
#define H2C(q, k) (*((const __half2*)&(q) + (k)))
#define ACCQ(q) { \
    float2 f0 = __half22float2(H2C(q,0)); \
    float2 f1 = __half22float2(H2C(q,1)); \
    float2 f2 = __half22float2(H2C(q,2)); \
    float2 f3 = __half22float2(H2C(q,3)); \
    a0+=f0.x; a1+=f0.y; a2+=f1.x; a3+=f1.y; \
    a4+=f2.x; a5+=f2.y; a6+=f3.x; a7+=f3.y; }
#define ACC4(q0, q1, q2, q3) { \
    __half2 s0 = __hadd2(__hadd2(H2C(q0,0), H2C(q1,0)), __hadd2(H2C(q2,0), H2C(q3,0))); \
    __half2 s1 = __hadd2(__hadd2(H2C(q0,1), H2C(q1,1)), __hadd2(H2C(q2,1), H2C(q3,1))); \
    __half2 s2 = __hadd2(__hadd2(H2C(q0,2), H2C(q1,2)), __hadd2(H2C(q2,2), H2C(q3,2))); \
    __half2 s3 = __hadd2(__hadd2(H2C(q0,3), H2C(q1,3)), __hadd2(H2C(q2,3), H2C(q3,3))); \
    float2 f0 = __half22float2(s0); float2 f1 = __half22float2(s1); \
    float2 f2 = __half22float2(s2); float2 f3 = __half22float2(s3); \
    a0+=f0.x; a1+=f0.y; a2+=f1.x; a3+=f1.y; \
    a4+=f2.x; a5+=f2.y; a6+=f3.x; a7+=f3.y; }

// ---------------- setup kernels ----------------

__global__ void k_zero() {
    int i = blockIdx.x * blockDim.x + threadIdx.x;
    int stride = gridDim.x * blockDim.x;
    for (int j = i; j < Nn;       j += stride) g_deg[j] = 0;
    for (int j = i; j < Bb * HID; j += stride) g_hg[j]  = 0.f;
    for (int j = i; j < NT;       j += stride) g_tilest[j] = 0u;
    if (i < Bb) { g_gfirst[i] = 0; g_glast[i] = 0; }
    if (i == 0) g_ticket = 0;
}

// degree histogram (atomic return = edge rank) + sorted-segment boundaries for counts
__global__ void k_deg(const int* __restrict__ dst,
                      const int* __restrict__ graph_ids) {
    int i = blockIdx.x * blockDim.x + threadIdx.x;
    if (i < Ee) g_rank[i] = atomicAdd(&g_deg[dst[i]], 1);
    if (i < Nn) {
        int g = graph_ids[i];
        if (i == 0 || graph_ids[i-1] != g)      g_gfirst[g] = i;
        if (i == Nn-1 || graph_ids[i+1] != g)   g_glast[g]  = i + 1;
    }
}

// single-pass decoupled-lookback exclusive scan
__global__ void __launch_bounds__(256) k_scan() {
    __shared__ int s_ticket, s_run;
    __shared__ int ssum[256];
    int tid = threadIdx.x;
    if (tid == 0) s_ticket = atomicAdd(&g_ticket, 1);
    __syncthreads();
    int t = s_ticket;
    int base = t * TILE + tid * 4;
    int d[4]; int s = 0;
    #pragma unroll
    for (int it = 0; it < 4; it++) {
        int idx = base + it;
        d[it] = (idx < Nn) ? g_deg[idx] : 0;
        s += d[it];
    }
    ssum[tid] = s; __syncthreads();
    #pragma unroll
    for (int off = 1; off < 256; off <<= 1) {
        int x = (tid >= off) ? ssum[tid - off] : 0;
        __syncthreads();
        ssum[tid] += x;
        __syncthreads();
    }
    int texcl = ssum[tid] - s;
    int total = ssum[255];
    if (tid == 0) {
        if (t == 0) {
            g_tilest[0] = (2u << 30) | (unsigned)total;
            s_run = 0;
        } else {
            g_tilest[t] = (1u << 30) | (unsigned)total;
            int run = 0, p = t - 1;
            while (true) {
                unsigned w = g_tilest[p];
                unsigned f = w >> 30;
                if (f == 2u) { run += (int)(w & 0x3FFFFFFFu); break; }
                if (f == 1u) { run += (int)(w & 0x3FFFFFFFu); p--; }
            }
            g_tilest[t] = (2u << 30) | (unsigned)(run + total);
            s_run = run;
        }
    }
    __syncthreads();
    int ex = s_run + texcl;
    #pragma unroll
    for (int it = 0; it < 4; it++) {
        int idx = base + it;
        if (idx < Nn) {
            g_rowptr[idx] = ex;
            int dd = d[it];
            g_dinv[idx] = (dd > 0) ? 1.0f / (float)dd : 0.0f;
            ex += dd;
        }
    }
}

__global__ void k_fill_gather(const int* __restrict__ src, const int* __restrict__ dst,
                              const int* __restrict__ node_ids,
                              const float4* __restrict__ emb) {
    int i = blockIdx.x * blockDim.x + threadIdx.x;
    if (i < Ee) {
        int d = dst[i];
        g_csr[g_rowptr[d] + g_rank[i]] = src[i];
    }
    if (i < Nn * 4) {
        int n = i >> 2, c = i & 3;
        float4 v0 = emb[node_ids[n] * 8 + c * 2 + 0];
        float4 v1 = emb[node_ids[n] * 8 + c * 2 + 1];
        uint4 o;
        o.x = ph2(v0.x, v0.y); o.y = ph2(v0.z, v0.w);
        o.z = ph2(v1.x, v1.y); o.w = ph2(v1.z, v1.w);
        g_h0h[n * 4 + c] = o;
    }
}

// ---------------- aggregation (pairwise fp16, fp32 outer) ----------------

__global__ void k_agg1() {
    int t = blockIdx.x * blockDim.x + threadIdx.x;
    if (t >= Nn * 4) return;
    int n = t >> 2, c = t & 3;
    int beg = g_rowptr[n], cnt = g_deg[n];
    float a0=0.f,a1=0.f,a2=0.f,a3=0.f,a4=0.f,a5=0.f,a6=0.f,a7=0.f;
    int i = 0;
    for (; i + 7 < cnt; i += 8) {
        int s0 = __ldg(&g_csr[beg+i+0]), s1 = __ldg(&g_csr[beg+i+1]);
        int s2 = __ldg(&g_csr[beg+i+2]), s3 = __ldg(&g_csr[beg+i+3]);
        int s4 = __ldg(&g_csr[beg+i+4]), s5 = __ldg(&g_csr[beg+i+5]);
        int s6 = __ldg(&g_csr[beg+i+6]), s7 = __ldg(&g_csr[beg+i+7]);
        uint4 q0 = g_h0h[s0*4+c], q1 = g_h0h[s1*4+c];
        uint4 q2 = g_h0h[s2*4+c], q3 = g_h0h[s3*4+c];
        uint4 q4 = g_h0h[s4*4+c], q5 = g_h0h[s5*4+c];
        uint4 q6 = g_h0h[s6*4+c], q7 = g_h0h[s7*4+c];
        ACC4(q0, q1, q2, q3)
        ACC4(q4, q5, q6, q7)
    }
    for (; i + 3 < cnt; i += 4) {
        int s0 = __ldg(&g_csr[beg+i+0]), s1 = __ldg(&g_csr[beg+i+1]);
        int s2 = __ldg(&g_csr[beg+i+2]), s3 = __ldg(&g_csr[beg+i+3]);
        uint4 q0 = g_h0h[s0*4+c], q1 = g_h0h[s1*4+c];
        uint4 q2 = g_h0h[s2*4+c], q3 = g_h0h[s3*4+c];
        ACC4(q0, q1, q2, q3)
    }
    for (; i < cnt; i++) {
        int s = __ldg(&g_csr[beg+i]);
        uint4 q = g_h0h[s*4+c];
        ACCQ(q)
    }
    float dinv = g_dinv[n];
    uint4 o;
    o.x = ph2(a0*dinv, a1*dinv); o.y = ph2(a2*dinv, a3*dinv);
    o.z = ph2(a4*dinv, a5*dinv); o.w = ph2(a6*dinv, a7*dinv);
    g_ag1h[n*4 + c] = o;
}

__global__ void k_agg2() {
    int t = blockIdx.x * blockDim.x + threadIdx.x;
    if (t >= Nn * 8) return;
    int n = t >> 3, c = t & 7;
    int beg = g_rowptr[n], cnt = g_deg[n];
    float a0=0.f,a1=0.f,a2=0.f,a3=0.f,a4=0.f,a5=0.f,a6=0.f,a7=0.f;
    int i = 0;
    for (; i + 7 < cnt; i += 8) {
        int s0 = __ldg(&g_csr[beg+i+0]), s1 = __ldg(&g_csr[beg+i+1]);
        int s2 = __ldg(&g_csr[beg+i+2]), s3 = __ldg(&g_csr[beg+i+3]);
        int s4 = __ldg(&g_csr[beg+i+4]), s5 = __ldg(&g_csr[beg+i+5]);
        int s6 = __ldg(&g_csr[beg+i+6]), s7 = __ldg(&g_csr[beg+i+7]);
        uint4 q0 = g_h1h[s0*8+c], q1 = g_h1h[s1*8+c];
        uint4 q2 = g_h1h[s2*8+c], q3 = g_h1h[s3*8+c];
        uint4 q4 = g_h1h[s4*8+c], q5 = g_h1h[s5*8+c];
        uint4 q6 = g_h1h[s6*8+c], q7 = g_h1h[s7*8+c];
        ACC4(q0, q1, q2, q3)
        ACC4(q4, q5, q6, q7)
    }
    for (; i + 3 < cnt; i += 4) {
        int s0 = __ldg(&g_csr[beg+i+0]), s1 = __ldg(&g_csr[beg+i+1]);
        int s2 = __ldg(&g_csr[beg+i+2]), s3 = __ldg(&g_csr[beg+i+3]);
        uint4 q0 = g_h1h[s0*8+c], q1 = g_h1h[s1*8+c];
        uint4 q2 = g_h1h[s2*8+c], q3 = g_h1h[s3*8+c];
        ACC4(q0, q1, q2, q3)
    }
    for (; i < cnt; i++) {
        int s = __ldg(&g_csr[beg+i]);
        uint4 q = g_h1h[s*8+c];
        ACCQ(q)
    }
    float dinv = g_dinv[n];
    uint4 o;
    o.x = ph2(a0*dinv, a1*dinv); o.y = ph2(a2*dinv, a3*dinv);
    o.z = ph2(a4*dinv, a5*dinv); o.w = ph2(a6*dinv, a7*dinv);
    g_ag2h[n*8 + c] = o;
}

// ---------------- dense updates: 2 nodes/thread, HALF-split, LDS.128 weights ------

__global__ void __launch_bounds__(256)
k_update1(const float* __restrict__ Wse, const float* __restrict__ Wne,
          const float* __restrict__ b) {
    __shared__ float sW[2 * EMB * HID];   // 16 KB
    __shared__ float sb[HID];
    int tid = threadIdx.x;
    for (int i = tid; i < EMB * HID; i += 256) { sW[i] = Wse[i]; sW[EMB*HID + i] = Wne[i]; }
    if (tid < HID) sb[tid] = b[tid];
    __syncthreads();

    int t = blockIdx.x * 256 + tid;
    if (t >= Nn / 2) return;          // Nn even
    int n0 = t * 2, n1 = n0 + 1;

    #pragma unroll 1
    for (int q = 0; q < 2; q++) {     // half = 32 output cols
        u64 acc0[16], acc1[16];
        #pragma unroll
        for (int j2 = 0; j2 < 16; j2++) {
            u64 bi = pack2(sb[q*32 + 2*j2], sb[q*32 + 2*j2 + 1]);
            acc0[j2] = bi; acc1[j2] = bi;
        }
        #pragma unroll 1
        for (int kk = 0; kk < 4; kk++) {
            uint4 qh0 = g_h0h[n0*4 + kk], qa0 = g_ag1h[n0*4 + kk];
            uint4 qh1 = g_h0h[n1*4 + kk], qa1 = g_ag1h[n1*4 + kk];
            #pragma unroll
            for (int ch = 0; ch < 8; ch++) {
                int k = kk*8 + ch;
                const ulonglong2* ws = (const ulonglong2*)&sW[k * HID + q*32];
                const ulonglong2* wn = (const ulonglong2*)&sW[(EMB + k) * HID + q*32];
                float h0 = hget(qh0, ch), a0f = hget(qa0, ch);
                float h1 = hget(qh1, ch), a1f = hget(qa1, ch);
                u64 bh0 = pack2(h0, h0), ba0 = pack2(a0f, a0f);
                u64 bh1 = pack2(h1, h1), ba1 = pack2(a1f, a1f);
                #pragma unroll
                for (int j4 = 0; j4 < 8; j4++) {
                    ulonglong2 w = ws[j4], v = wn[j4];
                    fma2(acc0[j4*2+0], bh0, w.x); fma2(acc0[j4*2+1], bh0, w.y);
                    fma2(acc1[j4*2+0], bh1, w.x); fma2(acc1[j4*2+1], bh1, w.y);
                    fma2(acc0[j4*2+0], ba0, v.x); fma2(acc0[j4*2+1], ba0, v.y);
                    fma2(acc1[j4*2+0], ba1, v.x); fma2(acc1[j4*2+1], ba1, v.y);
                }
            }
        }
        // store half: 32 fp16 = 4 uint4 per node
        #pragma unroll
        for (int s4 = 0; s4 < 4; s4++) {
            float x0,x1,x2,x3,x4,x5,x6,x7;
            unpack2(x0,x1, acc0[s4*4+0]); unpack2(x2,x3, acc0[s4*4+1]);
            unpack2(x4,x5, acc0[s4*4+2]); unpack2(x6,x7, acc0[s4*4+3]);
            uint4 o;
            o.x = ph2(fmaxf(x0,0.f), fmaxf(x1,0.f));
            o.y = ph2(fmaxf(x2,0.f), fmaxf(x3,0.f));
            o.z = ph2(fmaxf(x4,0.f), fmaxf(x5,0.f));
            o.w = ph2(fmaxf(x6,0.f), fmaxf(x7,0.f));
            g_h1h[n0*8 + q*4 + s4] = o;
            unpack2(x0,x1, acc1[s4*4+0]); unpack2(x2,x3, acc1[s4*4+1]);
            unpack2(x4,x5, acc1[s4*4+2]); unpack2(x6,x7, acc1[s4*4+3]);
            o.x = ph2(fmaxf(x0,0.f), fmaxf(x1,0.f));
            o.y = ph2(fmaxf(x2,0.f), fmaxf(x3,0.f));
            o.z = ph2(fmaxf(x4,0.f), fmaxf(x5,0.f));
            o.w = ph2(fmaxf(x6,0.f), fmaxf(x7,0.f));
            g_h1h[n1*8 + q*4 + s4] = o;
        }
    }
}

__global__ void __launch_bounds__(256)
k_update2(const float* __restrict__ Wse, const float* __restrict__ Wne,
          const float* __restrict__ b, const int* __restrict__ graph_ids) {
    __shared__ float sW[2 * HID * HID];   // 32 KB
    __shared__ float sb[HID];
    int tid = threadIdx.x;
    for (int i = tid; i < HID * HID; i += 256) { sW[i] = Wse[i]; sW[HID*HID + i] = Wne[i]; }
    if (tid < HID) sb[tid] = b[tid];
    __syncthreads();

    int t = blockIdx.x * 256 + tid;
    if (t >= Nn / 2) return;
    int n0 = t * 2, n1 = n0 + 1;
    int g0 = graph_ids[n0], g1 = graph_ids[n1];
    float4* hg0 = (float4*)&g_hg[g0 * HID];
    float4* hg1 = (float4*)&g_hg[g1 * HID];

    #pragma unroll 1
    for (int q = 0; q < 2; q++) {
        u64 acc0[16], acc1[16];
        #pragma unroll
        for (int j2 = 0; j2 < 16; j2++) {
            u64 bi = pack2(sb[q*32 + 2*j2], sb[q*32 + 2*j2 + 1]);
            acc0[j2] = bi; acc1[j2] = bi;
        }
        #pragma unroll 1
        for (int kk = 0; kk < 8; kk++) {
            uint4 qh0 = g_h1h[n0*8 + kk], qa0 = g_ag2h[n0*8 + kk];
            uint4 qh1 = g_h1h[n1*8 + kk], qa1 = g_ag2h[n1*8 + kk];
            #pragma unroll
            for (int ch = 0; ch < 8; ch++) {
                int k = kk*8 + ch;
                const ulonglong2* ws = (const ulonglong2*)&sW[k * HID + q*32];
                const ulonglong2* wn = (const ulonglong2*)&sW[(HID + k) * HID + q*32];
                float h0 = hget(qh0, ch), a0f = hget(qa0, ch);
                float h1 = hget(qh1, ch), a1f = hget(qa1, ch);
                u64 bh0 = pack2(h0, h0), ba0 = pack2(a0f, a0f);
                u64 bh1 = pack2(h1, h1), ba1 = pack2(a1f, a1f);
                #pragma unroll
                for (int j4 = 0; j4 < 8; j4++) {
                    ulonglong2 w = ws[j4], v = wn[j4];
                    fma2(acc0[j4*2+0], bh0, w.x); fma2(acc0[j4*2+1], bh0, w.y);
                    fma2(acc1[j4*2+0], bh1, w.x); fma2(acc1[j4*2+1], bh1, w.y);
                    fma2(acc0[j4*2+0], ba0, v.x); fma2(acc0[j4*2+1], ba0, v.y);
                    fma2(acc1[j4*2+0], ba1, v.x); fma2(acc1[j4*2+1], ba1, v.y);
                }
            }
        }
        // pool half: 32 floats = 8 float4 per node
        #pragma unroll
        for (int j4 = 0; j4 < 8; j4++) {
            float x0,x1,x2,x3;
            unpack2(x0, x1, acc0[j4*2+0]);
            unpack2(x2, x3, acc0[j4*2+1]);
            red4(&hg0[q*8 + j4], make_float4(fmaxf(x0,0.f), fmaxf(x1,0.f),
                                             fmaxf(x2,0.f), fmaxf(x3,0.f)));
            unpack2(x0, x1, acc1[j4*2+0]);
            unpack2(x2, x3, acc1[j4*2+1]);
            red4(&hg1[q*8 + j4], make_float4(fmaxf(x0,0.f), fmaxf(x1,0.f),
                                             fmaxf(x2,0.f), fmaxf(x3,0.f)));
        }
    }
}

// scorer (counts from sorted-segment boundaries)
__global__ void k_final(const float* __restrict__ Ws1, const float* __restrict__ bs1,
                        const float* __restrict__ Ws2, const float* __restrict__ bs2,
                        float* __restrict__ out) {
    __shared__ float sW[HID * HID];
    int tid = threadIdx.x;
    for (int i = tid; i < HID * HID; i += 64) sW[i] = Ws1[i];
    __syncthreads();

    int g = blockIdx.x * 64 + tid;
    if (g >= Bb) return;

    float cv = (float)(g_glast[g] - g_gfirst[g]);
    float inv = 1.0f / fmaxf(cv, 1.0f);
    float hv[HID];
    #pragma unroll
    for (int k = 0; k < HID; k++) hv[k] = g_hg[g * HID + k] * inv;

    float s = bs2[0];
    #pragma unroll 1
    for (int j = 0; j < HID; j++) {
        float t = bs1[j];
        #pragma unroll
        for (int k = 0; k < HID; k++) t += hv[k] * sW[k * HID + j];
        s += fmaxf(t, 0.f) * Ws2[j];
    }
    out[g] = s;
}

// ---------------- launcher ----------------
extern "C" void kernel_launch(void* const* d_in, const int* in_sizes, int n_in,
                              void* d_out, int out_size) {
    const int*    node_ids  = (const int*)   d_in[0];
    const int*    src       = (const int*)   d_in[1];
    const int*    dst       = (const int*)   d_in[2];
    const int*    graph_ids = (const int*)   d_in[3];
    const float4* emb       = (const float4*)d_in[4];
    const float*  W_self1   = (const float*) d_in[5];
    const float*  W_neigh1  = (const float*) d_in[6];
    const float*  b1        = (const float*) d_in[7];
    const float*  W_self2   = (const float*) d_in[8];
    const float*  W_neigh2  = (const float*) d_in[9];
    const float*  b2        = (const float*) d_in[10];
    const float*  Ws1       = (const float*) d_in[11];
    const float*  bs1       = (const float*) d_in[12];
    const float*  Ws2       = (const float*) d_in[13];
    const float*  bs2       = (const float*) d_in[14];
    float* out = (float*)d_out;

    k_zero       <<<512, 256>>>();                                      // 0
    k_deg        <<<(Ee + 255) / 256, 256>>>(dst, graph_ids);           // 1
    k_scan       <<<NT, 256>>>();                                       // 2
    k_fill_gather<<<(Ee + 255) / 256, 256>>>(src, dst, node_ids, emb);  // 3
    k_agg1       <<<(Nn * 4 + 255) / 256, 256>>>();                     // 4
    k_update1    <<<(Nn/2 + 255) / 256, 256>>>(W_self1, W_neigh1, b1);  // 5
    k_agg2       <<<(Nn * 8 + 255) / 256, 256>>>();                     // 6
    k_update2    <<<(Nn/2 + 255) / 256, 256>>>(W_self2, W_neigh2, b2, graph_ids); // 7
    k_final      <<<(Bb + 63) / 64, 64>>>(Ws1, bs1, Ws2, bs2, out);     // 8
}

// round 14
// speedup vs baseline: 1.8653x; 1.2996x over previous
#include <cuda_runtime.h>
#include <cuda_fp16.h>

typedef unsigned long long u64;
typedef unsigned int u32;

#define Nn   200000
#define Ee   3200000
#define Bb   512
#define EMB  32
#define HID  64
#define TILE 1024
#define NT   ((Nn + TILE - 1) / TILE)   // 196 scan tiles
#define NUB  ((Nn + 255) / 256)         // update blocks (256 nodes each)

// ---------------- scratch (device globals) ----------------
__device__ uint4 g_h0h [Nn * 4];          // 12.8 MB fp16 h0 (32 ch)
__device__ uint4 g_ag1h[Nn * 4];          // 12.8 MB fp16 agg1
__device__ uint4 g_h1h [Nn * 8];          // 25.6 MB fp16 h1 (64 ch)
__device__ uint4 g_ag2h[Nn * 8];          // 25.6 MB fp16 agg2
__device__ int   g_csr [Ee];
__device__ int   g_rank[Ee];
__device__ int   g_rowptr[Nn];
__device__ int   g_deg [Nn];
__device__ float g_dinv[Nn];
__device__ float g_hg  [Bb * HID];
__device__ int   g_gfirst[Bb];
__device__ int   g_glast [Bb];
__device__ volatile unsigned g_tilest[NT];
__device__ int   g_ticket;

// ---------------- helpers ----------------
__device__ __forceinline__ void red2(float* p, float x, float y) {
    asm volatile("red.global.add.v2.f32 [%0], {%1,%2};"
                 :: "l"(p), "f"(x), "f"(y) : "memory");
}
__device__ __forceinline__ unsigned ph2(float a, float b) {
    __half2 h = __floats2half2_rn(a, b); return *(unsigned*)&h;
}
__device__ __forceinline__ void mma16816(float& c0, float& c1, float& c2, float& c3,
                                         u32 a0, u32 a1, u32 a2, u32 a3,
                                         u32 b0, u32 b1) {
    asm volatile("mma.sync.aligned.m16n8k16.row.col.f32.f16.f16.f32 "
                 "{%0,%1,%2,%3},{%4,%5,%6,%7},{%8,%9},{%0,%1,%2,%3};"
                 : "+f"(c0), "+f"(c1), "+f"(c2), "+f"(c3)
                 : "r"(a0), "r"(a1), "r"(a2), "r"(a3), "r"(b0), "r"(b1));
}
#define H2C(q, k) (*((const __half2*)&(q) + (k)))
#define ACCQ(q) { \
    float2 f0 = __half22float2(H2C(q,0)); \
    float2 f1 = __half22float2(H2C(q,1)); \
    float2 f2 = __half22float2(H2C(q,2)); \
    float2 f3 = __half22float2(H2C(q,3)); \
    a0+=f0.x; a1+=f0.y; a2+=f1.x; a3+=f1.y; \
    a4+=f2.x; a5+=f2.y; a6+=f3.x; a7+=f3.y; }
#define ACC4(q0, q1, q2, q3) { \
    __half2 s0 = __hadd2(__hadd2(H2C(q0,0), H2C(q1,0)), __hadd2(H2C(q2,0), H2C(q3,0))); \
    __half2 s1 = __hadd2(__hadd2(H2C(q0,1), H2C(q1,1)), __hadd2(H2C(q2,1), H2C(q3,1))); \
    __half2 s2 = __hadd2(__hadd2(H2C(q0,2), H2C(q1,2)), __hadd2(H2C(q2,2), H2C(q3,2))); \
    __half2 s3 = __hadd2(__hadd2(H2C(q0,3), H2C(q1,3)), __hadd2(H2C(q2,3), H2C(q3,3))); \
    float2 f0 = __half22float2(s0); float2 f1 = __half22float2(s1); \
    float2 f2 = __half22float2(s2); float2 f3 = __half22float2(s3); \
    a0+=f0.x; a1+=f0.y; a2+=f1.x; a3+=f1.y; \
    a4+=f2.x; a5+=f2.y; a6+=f3.x; a7+=f3.y; }

// ---------------- setup kernels ----------------

__global__ void k_zero() {
    int i = blockIdx.x * blockDim.x + threadIdx.x;
    int stride = gridDim.x * blockDim.x;
    for (int j = i; j < Nn;       j += stride) g_deg[j] = 0;
    for (int j = i; j < Bb * HID; j += stride) g_hg[j]  = 0.f;
    for (int j = i; j < NT;       j += stride) g_tilest[j] = 0u;
    if (i < Bb) { g_gfirst[i] = 0; g_glast[i] = 0; }
    if (i == 0) g_ticket = 0;
}

__global__ void k_deg(const int* __restrict__ dst,
                      const int* __restrict__ graph_ids) {
    int i = blockIdx.x * blockDim.x + threadIdx.x;
    if (i < Ee) g_rank[i] = atomicAdd(&g_deg[dst[i]], 1);
    if (i < Nn) {
        int g = graph_ids[i];
        if (i == 0 || graph_ids[i-1] != g)      g_gfirst[g] = i;
        if (i == Nn-1 || graph_ids[i+1] != g)   g_glast[g]  = i + 1;
    }
}

__global__ void __launch_bounds__(256) k_scan() {
    __shared__ int s_ticket, s_run;
    __shared__ int ssum[256];
    int tid = threadIdx.x;
    if (tid == 0) s_ticket = atomicAdd(&g_ticket, 1);
    __syncthreads();
    int t = s_ticket;
    int base = t * TILE + tid * 4;
    int d[4]; int s = 0;
    #pragma unroll
    for (int it = 0; it < 4; it++) {
        int idx = base + it;
        d[it] = (idx < Nn) ? g_deg[idx] : 0;
        s += d[it];
    }
    ssum[tid] = s; __syncthreads();
    #pragma unroll
    for (int off = 1; off < 256; off <<= 1) {
        int x = (tid >= off) ? ssum[tid - off] : 0;
        __syncthreads();
        ssum[tid] += x;
        __syncthreads();
    }
    int texcl = ssum[tid] - s;
    int total = ssum[255];
    if (tid == 0) {
        if (t == 0) {
            g_tilest[0] = (2u << 30) | (unsigned)total;
            s_run = 0;
        } else {
            g_tilest[t] = (1u << 30) | (unsigned)total;
            int run = 0, p = t - 1;
            while (true) {
                unsigned w = g_tilest[p];
                unsigned f = w >> 30;
                if (f == 2u) { run += (int)(w & 0x3FFFFFFFu); break; }
                if (f == 1u) { run += (int)(w & 0x3FFFFFFFu); p--; }
            }
            g_tilest[t] = (2u << 30) | (unsigned)(run + total);
            s_run = run;
        }
    }
    __syncthreads();
    int ex = s_run + texcl;
    #pragma unroll
    for (int it = 0; it < 4; it++) {
        int idx = base + it;
        if (idx < Nn) {
            g_rowptr[idx] = ex;
            int dd = d[it];
            g_dinv[idx] = (dd > 0) ? 1.0f / (float)dd : 0.0f;
            ex += dd;
        }
    }
}

__global__ void k_fill_gather(const int* __restrict__ src, const int* __restrict__ dst,
                              const int* __restrict__ node_ids,
                              const float4* __restrict__ emb) {
    int i = blockIdx.x * blockDim.x + threadIdx.x;
    if (i < Ee) {
        int d = dst[i];
        g_csr[g_rowptr[d] + g_rank[i]] = src[i];
    }
    if (i < Nn * 4) {
        int n = i >> 2, c = i & 3;
        float4 v0 = emb[node_ids[n] * 8 + c * 2 + 0];
        float4 v1 = emb[node_ids[n] * 8 + c * 2 + 1];
        uint4 o;
        o.x = ph2(v0.x, v0.y); o.y = ph2(v0.z, v0.w);
        o.z = ph2(v1.x, v1.y); o.w = ph2(v1.z, v1.w);
        g_h0h[n * 4 + c] = o;
    }
}

// ---------------- aggregation (pairwise fp16, fp32 outer) ----------------

__global__ void k_agg1() {
    int t = blockIdx.x * blockDim.x + threadIdx.x;
    if (t >= Nn * 4) return;
    int n = t >> 2, c = t & 3;
    int beg = g_rowptr[n], cnt = g_deg[n];
    float a0=0.f,a1=0.f,a2=0.f,a3=0.f,a4=0.f,a5=0.f,a6=0.f,a7=0.f;
    int i = 0;
    for (; i + 7 < cnt; i += 8) {
        int s0 = __ldg(&g_csr[beg+i+0]), s1 = __ldg(&g_csr[beg+i+1]);
        int s2 = __ldg(&g_csr[beg+i+2]), s3 = __ldg(&g_csr[beg+i+3]);
        int s4 = __ldg(&g_csr[beg+i+4]), s5 = __ldg(&g_csr[beg+i+5]);
        int s6 = __ldg(&g_csr[beg+i+6]), s7 = __ldg(&g_csr[beg+i+7]);
        uint4 q0 = g_h0h[s0*4+c], q1 = g_h0h[s1*4+c];
        uint4 q2 = g_h0h[s2*4+c], q3 = g_h0h[s3*4+c];
        uint4 q4 = g_h0h[s4*4+c], q5 = g_h0h[s5*4+c];
        uint4 q6 = g_h0h[s6*4+c], q7 = g_h0h[s7*4+c];
        ACC4(q0, q1, q2, q3)
        ACC4(q4, q5, q6, q7)
    }
    for (; i + 3 < cnt; i += 4) {
        int s0 = __ldg(&g_csr[beg+i+0]), s1 = __ldg(&g_csr[beg+i+1]);
        int s2 = __ldg(&g_csr[beg+i+2]), s3 = __ldg(&g_csr[beg+i+3]);
        uint4 q0 = g_h0h[s0*4+c], q1 = g_h0h[s1*4+c];
        uint4 q2 = g_h0h[s2*4+c], q3 = g_h0h[s3*4+c];
        ACC4(q0, q1, q2, q3)
    }
    for (; i < cnt; i++) {
        int s = __ldg(&g_csr[beg+i]);
        uint4 q = g_h0h[s*4+c];
        ACCQ(q)
    }
    float dinv = g_dinv[n];
    uint4 o;
    o.x = ph2(a0*dinv, a1*dinv); o.y = ph2(a2*dinv, a3*dinv);
    o.z = ph2(a4*dinv, a5*dinv); o.w = ph2(a6*dinv, a7*dinv);
    g_ag1h[n*4 + c] = o;
}

__global__ void k_agg2() {
    int t = blockIdx.x * blockDim.x + threadIdx.x;
    if (t >= Nn * 8) return;
    int n = t >> 3, c = t & 7;
    int beg = g_rowptr[n], cnt = g_deg[n];
    float a0=0.f,a1=0.f,a2=0.f,a3=0.f,a4=0.f,a5=0.f,a6=0.f,a7=0.f;
    int i = 0;
    for (; i + 7 < cnt; i += 8) {
        int s0 = __ldg(&g_csr[beg+i+0]), s1 = __ldg(&g_csr[beg+i+1]);
        int s2 = __ldg(&g_csr[beg+i+2]), s3 = __ldg(&g_csr[beg+i+3]);
        int s4 = __ldg(&g_csr[beg+i+4]), s5 = __ldg(&g_csr[beg+i+5]);
        int s6 = __ldg(&g_csr[beg+i+6]), s7 = __ldg(&g_csr[beg+i+7]);
        uint4 q0 = g_h1h[s0*8+c], q1 = g_h1h[s1*8+c];
        uint4 q2 = g_h1h[s2*8+c], q3 = g_h1h[s3*8+c];
        uint4 q4 = g_h1h[s4*8+c], q5 = g_h1h[s5*8+c];
        uint4 q6 = g_h1h[s6*8+c], q7 = g_h1h[s7*8+c];
        ACC4(q0, q1, q2, q3)
        ACC4(q4, q5, q6, q7)
    }
    for (; i + 3 < cnt; i += 4) {
        int s0 = __ldg(&g_csr[beg+i+0]), s1 = __ldg(&g_csr[beg+i+1]);
        int s2 = __ldg(&g_csr[beg+i+2]), s3 = __ldg(&g_csr[beg+i+3]);
        uint4 q0 = g_h1h[s0*8+c], q1 = g_h1h[s1*8+c];
        uint4 q2 = g_h1h[s2*8+c], q3 = g_h1h[s3*8+c];
        ACC4(q0, q1, q2, q3)
    }
    for (; i < cnt; i++) {
        int s = __ldg(&g_csr[beg+i]);
        uint4 q = g_h1h[s*8+c];
        ACCQ(q)
    }
    float dinv = g_dinv[n];
    uint4 o;
    o.x = ph2(a0*dinv, a1*dinv); o.y = ph2(a2*dinv, a3*dinv);
    o.z = ph2(a4*dinv, a5*dinv); o.w = ph2(a6*dinv, a7*dinv);
    g_ag2h[n*8 + c] = o;
}

// ---------------- tensor-core dense updates (mma.sync m16n8k16) ----------------
// Layer1: A = [h0 | agg1] fp16 (K=64), B = fp16([Wself1; Wneigh1]) transposed in smem.
// Weights stored smem [n][k], stride chosen for conflict-free B-fragment LDS.

__global__ void __launch_bounds__(256)
k_update1_mma(const float* __restrict__ Wse, const float* __restrict__ Wne,
              const float* __restrict__ b) {
    const int K = 2 * EMB;          // 64
    const int WS = 72;              // smem row stride (halves): banks 4n+c distinct
    __shared__ __half sWt[HID * WS];   // 9.2 KB
    __shared__ float sb[HID];
    int tid = threadIdx.x;
    for (int i = tid; i < HID * K; i += 256) {
        int n = i >> 6, k = i & 63;
        float w = (k < EMB) ? Wse[k * HID + n] : Wne[(k - EMB) * HID + n];
        sWt[n * WS + k] = __float2half(w);
    }
    if (tid < HID) sb[tid] = b[tid];
    __syncthreads();

    int warp = tid >> 5, lane = tid & 31;
    int gid = lane >> 2, c = lane & 3;
    const __half* fh = (const __half*)g_h0h;    // node stride 32 halves
    const __half* fa = (const __half*)g_ag1h;
    __half* out = (__half*)g_h1h;               // node stride 64 halves

    #pragma unroll 1
    for (int mt = 0; mt < 2; mt++) {
        int m = blockIdx.x * 256 + warp * 32 + mt * 16;
        if (m >= Nn) break;
        int r0 = m + gid, r1 = r0 + 8;

        float acc[8][4];
        #pragma unroll
        for (int nt = 0; nt < 8; nt++) {
            float b0 = sb[nt*8 + 2*c], b1 = sb[nt*8 + 2*c + 1];
            acc[nt][0] = b0; acc[nt][1] = b1; acc[nt][2] = b0; acc[nt][3] = b1;
        }

        #pragma unroll
        for (int kk = 0; kk < 4; kk++) {
            int k0 = kk * 16;
            const __half* src = (kk < 2) ? fh : fa;
            int koff = (kk < 2) ? k0 : k0 - EMB;
            u32 a0 = *(const u32*)(src + r0*EMB + koff + 2*c);
            u32 a1 = *(const u32*)(src + r1*EMB + koff + 2*c);
            u32 a2 = *(const u32*)(src + r0*EMB + koff + 8 + 2*c);
            u32 a3 = *(const u32*)(src + r1*EMB + koff + 8 + 2*c);
            #pragma unroll
            for (int nt = 0; nt < 8; nt++) {
                int n = nt*8 + gid;
                u32 b0 = *(const u32*)&sWt[n * WS + k0 + 2*c];
                u32 b1 = *(const u32*)&sWt[n * WS + k0 + 8 + 2*c];
                mma16816(acc[nt][0], acc[nt][1], acc[nt][2], acc[nt][3],
                         a0, a1, a2, a3, b0, b1);
            }
        }

        #pragma unroll
        for (int nt = 0; nt < 8; nt++) {
            int col = nt*8 + 2*c;
            *(u32*)(out + r0*HID + col) = ph2(fmaxf(acc[nt][0],0.f), fmaxf(acc[nt][1],0.f));
            *(u32*)(out + r1*HID + col) = ph2(fmaxf(acc[nt][2],0.f), fmaxf(acc[nt][3],0.f));
        }
    }
}

// Layer2: A = [h1 | agg2] (K=128); epilogue pools relu(out) into g_hg via red.v2.
__global__ void __launch_bounds__(256)
k_update2_mma(const float* __restrict__ Wse, const float* __restrict__ Wne,
              const float* __restrict__ b, const int* __restrict__ graph_ids) {
    const int K = 2 * HID;          // 128
    const int WS = 136;             // stride halves: 68 words -> banks 4n+c distinct
    __shared__ __half sWt[HID * WS];   // 17.4 KB
    __shared__ float sb[HID];
    int tid = threadIdx.x;
    for (int i = tid; i < HID * K; i += 256) {
        int n = i >> 7, k = i & 127;
        float w = (k < HID) ? Wse[k * HID + n] : Wne[(k - HID) * HID + n];
        sWt[n * WS + k] = __float2half(w);
    }
    if (tid < HID) sb[tid] = b[tid];
    __syncthreads();

    int warp = tid >> 5, lane = tid & 31;
    int gid = lane >> 2, c = lane & 3;
    const __half* fh = (const __half*)g_h1h;    // node stride 64 halves
    const __half* fa = (const __half*)g_ag2h;

    #pragma unroll 1
    for (int mt = 0; mt < 2; mt++) {
        int m = blockIdx.x * 256 + warp * 32 + mt * 16;
        if (m >= Nn) break;
        int r0 = m + gid, r1 = r0 + 8;
        int g0 = graph_ids[r0], g1 = graph_ids[r1];

        float acc[8][4];
        #pragma unroll
        for (int nt = 0; nt < 8; nt++) {
            float b0 = sb[nt*8 + 2*c], b1 = sb[nt*8 + 2*c + 1];
            acc[nt][0] = b0; acc[nt][1] = b1; acc[nt][2] = b0; acc[nt][3] = b1;
        }

        #pragma unroll
        for (int kk = 0; kk < 8; kk++) {
            int k0 = kk * 16;
            const __half* src = (kk < 4) ? fh : fa;
            int koff = (kk < 4) ? k0 : k0 - HID;
            u32 a0 = *(const u32*)(src + r0*HID + koff + 2*c);
            u32 a1 = *(const u32*)(src + r1*HID + koff + 2*c);
            u32 a2 = *(const u32*)(src + r0*HID + koff + 8 + 2*c);
            u32 a3 = *(const u32*)(src + r1*HID + koff + 8 + 2*c);
            #pragma unroll
            for (int nt = 0; nt < 8; nt++) {
                int n = nt*8 + gid;
                u32 b0 = *(const u32*)&sWt[n * WS + k0 + 2*c];
                u32 b1 = *(const u32*)&sWt[n * WS + k0 + 8 + 2*c];
                mma16816(acc[nt][0], acc[nt][1], acc[nt][2], acc[nt][3],
                         a0, a1, a2, a3, b0, b1);
            }
        }

        #pragma unroll
        for (int nt = 0; nt < 8; nt++) {
            int col = nt*8 + 2*c;
            red2(&g_hg[g0*HID + col], fmaxf(acc[nt][0],0.f), fmaxf(acc[nt][1],0.f));
            red2(&g_hg[g1*HID + col], fmaxf(acc[nt][2],0.f), fmaxf(acc[nt][3],0.f));
        }
    }
}

// scorer (counts from sorted-segment boundaries)
__global__ void k_final(const float* __restrict__ Ws1, const float* __restrict__ bs1,
                        const float* __restrict__ Ws2, const float* __restrict__ bs2,
                        float* __restrict__ out) {
    __shared__ float sW[HID * HID];
    int tid = threadIdx.x;
    for (int i = tid; i < HID * HID; i += 64) sW[i] = Ws1[i];
    __syncthreads();

    int g = blockIdx.x * 64 + tid;
    if (g >= Bb) return;

    float cv = (float)(g_glast[g] - g_gfirst[g]);
    float inv = 1.0f / fmaxf(cv, 1.0f);
    float hv[HID];
    #pragma unroll
    for (int k = 0; k < HID; k++) hv[k] = g_hg[g * HID + k] * inv;

    float s = bs2[0];
    #pragma unroll 1
    for (int j = 0; j < HID; j++) {
        float t = bs1[j];
        #pragma unroll
        for (int k = 0; k < HID; k++) t += hv[k] * sW[k * HID + j];
        s += fmaxf(t, 0.f) * Ws2[j];
    }
    out[g] = s;
}

// ---------------- launcher ----------------
extern "C" void kernel_launch(void* const* d_in, const int* in_sizes, int n_in,
                              void* d_out, int out_size) {
    const int*    node_ids  = (const int*)   d_in[0];
    const int*    src       = (const int*)   d_in[1];
    const int*    dst       = (const int*)   d_in[2];
    const int*    graph_ids = (const int*)   d_in[3];
    const float4* emb       = (const float4*)d_in[4];
    const float*  W_self1   = (const float*) d_in[5];
    const float*  W_neigh1  = (const float*) d_in[6];
    const float*  b1        = (const float*) d_in[7];
    const float*  W_self2   = (const float*) d_in[8];
    const float*  W_neigh2  = (const float*) d_in[9];
    const float*  b2        = (const float*) d_in[10];
    const float*  Ws1       = (const float*) d_in[11];
    const float*  bs1       = (const float*) d_in[12];
    const float*  Ws2       = (const float*) d_in[13];
    const float*  bs2       = (const float*) d_in[14];
    float* out = (float*)d_out;

    k_zero       <<<512, 256>>>();                                      // 0
    k_deg        <<<(Ee + 255) / 256, 256>>>(dst, graph_ids);           // 1
    k_scan       <<<NT, 256>>>();                                       // 2
    k_fill_gather<<<(Ee + 255) / 256, 256>>>(src, dst, node_ids, emb);  // 3
    k_agg1       <<<(Nn * 4 + 255) / 256, 256>>>();                     // 4
    k_update1_mma<<<NUB, 256>>>(W_self1, W_neigh1, b1);                 // 5
    k_agg2       <<<(Nn * 8 + 255) / 256, 256>>>();                     // 6
    k_update2_mma<<<NUB, 256>>>(W_self2, W_neigh2, b2, graph_ids);      // 7
    k_final      <<<(Bb + 63) / 64, 64>>>(Ws1, bs1, Ws2, bs2, out);     // 8
}